// round 13
// baseline (speedup 1.0000x reference)
#include <cuda_runtime.h>
#include <cuda_bf16.h>
#include <cuda_fp16.h>
#include <math.h>
#include <stdint.h>

// ---------------------------------------------------------------------------
// DGCNN discriminator, B=16, N=1024, K=20.
// Round 13: split-K W4 GEMM — first K-half (cat cols 0:256, ready after
// layer 3) runs on side stream s2 overlapped with the whole layer-4 A-path;
// second K-half adds the partial (Cin) and does the fused column-max.
// Kernels otherwise identical to R12.
// ---------------------------------------------------------------------------

#define BB 16
#define NN 1024
#define KNNK 20
#define CATC 512

__device__ float g_G[BB * NN * NN];
__device__ float g_cat[BB * NN * CATC];
__device__ float g_uv[BB * NN * 512];
__device__ float g_h0[BB * NN * 1024];     // W4 partial sums (split-K)
__device__ float g_xx[BB * NN];
__device__ int   g_idx[BB * NN * KNNK];
__device__ float g_Wuv[512 * 256];
__device__ unsigned int g_zenc[BB * 1024];
__device__ float g_z[BB * 1088];
__device__ float g_ye0[BB * 16];
__device__ float g_z1[BB * 512];
__device__ float g_z2[BB * 256];

__device__ __forceinline__ unsigned int ord_float(float v) {
    unsigned int u = __float_as_uint(v);
    return (u & 0x80000000u) ? ~u : (u | 0x80000000u);
}
__device__ __forceinline__ float ord_decode(unsigned int e) {
    unsigned int u = (e & 0x80000000u) ? (e ^ 0x80000000u) : ~e;
    return __uint_as_float(u);
}

// ---------------- warp-MMA primitives (baseline PTX, sm_80+) ---------------
__device__ __forceinline__ void ldsm4(uint32_t* r, const void* p) {
    uint32_t addr = (uint32_t)__cvta_generic_to_shared(p);
    asm volatile("ldmatrix.sync.aligned.m8n8.x4.shared.b16 {%0,%1,%2,%3}, [%4];"
                 : "=r"(r[0]), "=r"(r[1]), "=r"(r[2]), "=r"(r[3]) : "r"(addr));
}
__device__ __forceinline__ void mma_f16(float* c, const uint32_t* a,
                                        const uint32_t* b) {
    asm volatile(
        "mma.sync.aligned.m16n8k16.row.col.f32.f16.f16.f32 "
        "{%0,%1,%2,%3}, {%4,%5,%6,%7}, {%8,%9}, {%0,%1,%2,%3};"
        : "+f"(c[0]), "+f"(c[1]), "+f"(c[2]), "+f"(c[3])
        : "r"(a[0]), "r"(a[1]), "r"(a[2]), "r"(a[3]), "r"(b[0]), "r"(b[1]));
}
__device__ __forceinline__ uint32_t packh2(float x, float y) {
    __half2 v = __floats2half2_rn(x, y);
    uint32_t r; memcpy(&r, &v, 4); return r;
}
__device__ __forceinline__ void split2h(float a, float& h, float& l) {
    h = __half2float(__float2half_rn(a));
    l = a - h;
}

#define LDS2 40
#define TILE2 (128 * LDS2)
#define SMEM_MMA (2 * TILE2 * 2)    // 20480 B

// ---------------------------------------------------------------------------
// C[M,N] = A[M,Kd] @ W[N,Kd]^T (+ Cin), fp32 in/out, 3-term fp16 split.
// EPI==0: store C.  EPI==1: (acc += Cin if given) then ord-atomicMax column
// max into zenc[(row0>>10)*1024 + col].
// ---------------------------------------------------------------------------
template<int EPI>
__global__ __launch_bounds__(256, 2)
void mma_gemm(const float* __restrict__ A, const float* __restrict__ Wt,
              float* __restrict__ C, unsigned int* __restrict__ zenc,
              const float* __restrict__ Cin,
              int Kd, int lda, int ldw, int ldc,
              long bA, long bW, long bC)
{
    extern __shared__ __half dsm[];
    __half* As = dsm;            // [128][LDS2]
    __half* Bs = dsm + TILE2;    // [128][LDS2]

    int bz = blockIdx.z;
    A  += (long)bz * bA;
    Wt += (long)bz * bW;
    C  += (long)bz * bC;

    int tid = threadIdx.x;
    int lane = tid & 31, wid = tid >> 5;
    int warpm = wid >> 2;
    int warpn = wid & 3;
    int row0 = blockIdx.y * 128, col0 = blockIdx.x * 128;

    int lr = tid >> 1;
    int kh = (tid & 1) << 3;
    const float* Ar = A  + (long)(row0 + lr) * lda;
    const float* Wr = Wt + (long)(col0 + lr) * ldw;
    const bool vec = ((lda & 3) == 0) && ((ldw & 3) == 0) && ((Kd & 15) == 0);

    float acc[4][4][4];
    #pragma unroll
    for (int i = 0; i < 4; i++)
        #pragma unroll
        for (int j = 0; j < 4; j++)
            #pragma unroll
            for (int q = 0; q < 4; q++) acc[i][j][q] = 0.f;

    int ntiles = (Kd + 15) >> 4;
    float fa[8], fb[8];

    {
        if (vec) {
            *(float4*)&fa[0] = *(const float4*)(Ar + kh);
            *(float4*)&fa[4] = *(const float4*)(Ar + kh + 4);
            *(float4*)&fb[0] = *(const float4*)(Wr + kh);
            *(float4*)&fb[4] = *(const float4*)(Wr + kh + 4);
        } else {
            #pragma unroll
            for (int q = 0; q < 8; q++) {
                int gk = kh + q;
                fa[q] = (gk < Kd) ? Ar[gk] : 0.f;
                fb[q] = (gk < Kd) ? Wr[gk] : 0.f;
            }
        }
    }

    for (int t = 0; t < ntiles; t++) {
        {
            float ah[8], al[8], bh[8], bl[8];
            #pragma unroll
            for (int q = 0; q < 8; q++) {
                split2h(fa[q], ah[q], al[q]);
                split2h(fb[q], bh[q], bl[q]);
            }
            int rb = lr * LDS2 + kh;
            #pragma unroll
            for (int j = 0; j < 4; j++) {
                int c = rb + 2 * j;
                *(uint32_t*)&As[c +  0] = packh2(ah[2 * j], ah[2 * j + 1]);
                *(uint32_t*)&As[c + 16] = packh2(al[2 * j], al[2 * j + 1]);
                *(uint32_t*)&Bs[c +  0] = packh2(bh[2 * j], bh[2 * j + 1]);
                *(uint32_t*)&Bs[c + 16] = packh2(bl[2 * j], bl[2 * j + 1]);
            }
        }
        __syncthreads();

        if (t + 1 < ntiles) {
            int k0 = (t + 1) << 4;
            if (vec) {
                *(float4*)&fa[0] = *(const float4*)(Ar + k0 + kh);
                *(float4*)&fa[4] = *(const float4*)(Ar + k0 + kh + 4);
                *(float4*)&fb[0] = *(const float4*)(Wr + k0 + kh);
                *(float4*)&fb[4] = *(const float4*)(Wr + k0 + kh + 4);
            } else {
                #pragma unroll
                for (int q = 0; q < 8; q++) {
                    int gk = k0 + kh + q;
                    fa[q] = (gk < Kd) ? Ar[gk] : 0.f;
                    fb[q] = (gk < Kd) ? Wr[gk] : 0.f;
                }
            }
        }

        {
            int arow = warpm * 64 + (lane & 15);
            int acol = (lane >> 4) << 3;
            int brow = warpn * 32 + (lane & 15);

            uint32_t afh[4][4], afl[4][4];
            uint32_t bfh[4][2], bfl[4][2];

            #pragma unroll
            for (int mi = 0; mi < 4; mi++)
                ldsm4(afh[mi], &As[(arow + mi * 16) * LDS2 + acol]);
            #pragma unroll
            for (int nq = 0; nq < 2; nq++) {
                uint32_t tt[4];
                ldsm4(tt, &Bs[(brow + nq * 16) * LDS2 + acol]);
                bfh[2 * nq][0] = tt[0]; bfh[2 * nq][1] = tt[2];
                bfh[2 * nq + 1][0] = tt[1]; bfh[2 * nq + 1][1] = tt[3];
            }
            #pragma unroll
            for (int mi = 0; mi < 4; mi++)
                #pragma unroll
                for (int nj = 0; nj < 4; nj++)
                    mma_f16(acc[mi][nj], afh[mi], bfh[nj]);

            #pragma unroll
            for (int nq = 0; nq < 2; nq++) {
                uint32_t tt[4];
                ldsm4(tt, &Bs[(brow + nq * 16) * LDS2 + 16 + acol]);
                bfl[2 * nq][0] = tt[0]; bfl[2 * nq][1] = tt[2];
                bfl[2 * nq + 1][0] = tt[1]; bfl[2 * nq + 1][1] = tt[3];
            }
            #pragma unroll
            for (int mi = 0; mi < 4; mi++)
                #pragma unroll
                for (int nj = 0; nj < 4; nj++)
                    mma_f16(acc[mi][nj], afh[mi], bfl[nj]);

            #pragma unroll
            for (int mi = 0; mi < 4; mi++)
                ldsm4(afl[mi], &As[(arow + mi * 16) * LDS2 + 16 + acol]);
            #pragma unroll
            for (int mi = 0; mi < 4; mi++)
                #pragma unroll
                for (int nj = 0; nj < 4; nj++)
                    mma_f16(acc[mi][nj], afl[mi], bfh[nj]);
        }
        __syncthreads();
    }

    int g = lane >> 2, tg = lane & 3;
    if (EPI == 0) {
        #pragma unroll
        for (int mi = 0; mi < 4; mi++) {
            int r = row0 + warpm * 64 + mi * 16 + g;
            #pragma unroll
            for (int nj = 0; nj < 4; nj++) {
                int c = col0 + warpn * 32 + nj * 8 + tg * 2;
                *(float2*)&C[(long)r * ldc + c] =
                    make_float2(acc[mi][nj][0], acc[mi][nj][1]);
                *(float2*)&C[(long)(r + 8) * ldc + c] =
                    make_float2(acc[mi][nj][2], acc[mi][nj][3]);
            }
        }
    } else {
        if (Cin) {
            #pragma unroll
            for (int mi = 0; mi < 4; mi++) {
                int r = row0 + warpm * 64 + mi * 16 + g;
                #pragma unroll
                for (int nj = 0; nj < 4; nj++) {
                    int c = col0 + warpn * 32 + nj * 8 + tg * 2;
                    float2 c01 = *(const float2*)&Cin[(long)r * ldc + c];
                    float2 c23 = *(const float2*)&Cin[(long)(r + 8) * ldc + c];
                    acc[mi][nj][0] += c01.x;
                    acc[mi][nj][1] += c01.y;
                    acc[mi][nj][2] += c23.x;
                    acc[mi][nj][3] += c23.y;
                }
            }
        }
        int bidx = row0 >> 10;
        #pragma unroll
        for (int nj = 0; nj < 4; nj++) {
            #pragma unroll
            for (int h = 0; h < 2; h++) {
                float v = fmaxf(acc[0][nj][h], acc[0][nj][h + 2]);
                #pragma unroll
                for (int mi = 1; mi < 4; mi++)
                    v = fmaxf(v, fmaxf(acc[mi][nj][h], acc[mi][nj][h + 2]));
                v = fmaxf(v, __shfl_xor_sync(0xFFFFFFFFu, v, 4));
                v = fmaxf(v, __shfl_xor_sync(0xFFFFFFFFu, v, 8));
                v = fmaxf(v, __shfl_xor_sync(0xFFFFFFFFu, v, 16));
                if (lane < 4)
                    atomicMax(&zenc[bidx * 1024 + col0 + warpn * 32 + nj * 8 +
                                    lane * 2 + h],
                              ord_float(v));
            }
        }
    }
}

// ---------------------------------------------------------------------------
__global__ void xx_kernel(const float* __restrict__ feat, int lda, int d,
                          float* __restrict__ xx)
{
    int p = blockIdx.x * blockDim.x + threadIdx.x;
    if (p >= BB * NN) return;
    const float* r = feat + (long)p * lda;
    float s = 0.f;
    for (int c = 0; c < d; c++) s = fmaf(r[c], r[c], s);
    xx[p] = s;
}

// Warp-per-row top-20 (register-resident, lazy top-2, exact jax tie-break).
__global__ __launch_bounds__(256)
void topk_kernel(const float* __restrict__ G, const float* __restrict__ xx,
                 int* __restrict__ idx)
{
    int warp = threadIdx.x >> 5, lane = threadIdx.x & 31;
    int row = blockIdx.x * 8 + warp;
    int b = row >> 10, i = row & 1023;
    const float* Grow = G + (long)row * NN;
    const float* xxb  = xx + (b << 10);
    float xi = xxb[i];

    float v[32];
    #pragma unroll
    for (int q = 0; q < 32; q++) {
        int j = q * 32 + lane;
        float inner = -2.0f * Grow[j];
        v[q] = -xi - inner - xxb[j];
    }

    float m1v = v[0], m2v = -__builtin_huge_valf();
    int m1q = 0, m2q = -1;
    #pragma unroll
    for (int q = 1; q < 32; q++) {
        if (v[q] > m1v) { m2v = m1v; m2q = m1q; m1v = v[q]; m1q = q; }
        else if (v[q] > m2v) { m2v = v[q]; m2q = q; }
    }

    int* out = idx + (long)row * KNNK;
    for (int kk = 0; kk < KNNK; kk++) {
        unsigned long long key =
            ((unsigned long long)ord_float(m1v) << 32)
            | (unsigned int)(0xFFFFFFFFu - (unsigned int)(m1q * 32 + lane));
        unsigned long long best = key;
        #pragma unroll
        for (int s = 16; s > 0; s >>= 1) {
            unsigned long long o = __shfl_xor_sync(0xFFFFFFFFu, best, s);
            if (o > best) best = o;
        }
        if (lane == 0)
            out[kk] = (int)(0xFFFFFFFFu - (unsigned int)(best & 0xFFFFFFFFu));

        if (key == best) {
            #pragma unroll
            for (int q = 0; q < 32; q++)
                if (q == m1q) v[q] = -__builtin_huge_valf();
            if (m2q >= 0) {
                m1v = m2v; m1q = m2q; m2q = -1;
            } else {
                m1v = v[0]; m1q = 0;
                m2v = -__builtin_huge_valf(); m2q = -1;
                #pragma unroll
                for (int q = 1; q < 32; q++) {
                    if (v[q] > m1v) { m2v = m1v; m2q = m1q; m1v = v[q]; m1q = q; }
                    else if (v[q] > m2v) { m2v = v[q]; m2q = q; }
                }
            }
        }
    }
}

__global__ void wuv_kernel(const float* __restrict__ W, float* __restrict__ Wuv,
                           int outc, int d)
{
    int t = blockIdx.x * blockDim.x + threadIdx.x;
    if (t >= 2 * outc * d) return;
    int r = t / d, c = t - r * d;
    if (r < outc) Wuv[t] = W[(long)r * 2 * d + c];
    else {
        int o = r - outc;
        Wuv[t] = W[(long)o * 2 * d + d + c] - W[(long)o * 2 * d + c];
    }
}

__global__ void gather_max_kernel(const float* __restrict__ uv,
                                  const int* __restrict__ idx,
                                  float* __restrict__ outp, int outc)
{
    int p = blockIdx.x;
    int b = p >> 10;
    int o = threadIdx.x;
    if (o >= outc) return;
    int ldu = 2 * outc;
    float vi = uv[(long)p * ldu + outc + o];
    const int* ip = idx + (long)p * KNNK;
    float m = -__builtin_huge_valf();
    #pragma unroll 4
    for (int kk = 0; kk < KNNK; kk++) {
        int j = ip[kk];
        float t = uv[((long)(b << 10) + j) * ldu + o] + vi;
        t = (t >= 0.f) ? t : 0.2f * t;
        m = fmaxf(m, t);
    }
    outp[(long)p * CATC + o] = m;
}

__global__ void zenc_init_kernel(unsigned int* __restrict__ zenc)
{
    int t = blockIdx.x * blockDim.x + threadIdx.x;
    if (t < BB * 1024) zenc[t] = 0u;
}

__global__ void zenc_decode_kernel(const unsigned int* __restrict__ zenc,
                                   float* __restrict__ z)
{
    int t = blockIdx.x * blockDim.x + threadIdx.x;
    if (t >= BB * 1024) return;
    int b = t >> 10, o = t & 1023;
    float m = ord_decode(zenc[t]);
    m = (m >= 0.f) ? m : 0.2f * m;
    z[b * 1088 + o] = m;
}

__global__ void fc_kernel(const float* __restrict__ A, int lda,
                          const float* __restrict__ W,
                          const float* __restrict__ bias,
                          float* __restrict__ C, int ldc,
                          int Bn, int O, int Kd, int relu)
{
    int t = blockIdx.x * blockDim.x + threadIdx.x;
    if (t >= Bn * O) return;
    int b = t / O, o = t - b * O;
    const float* a = A + (long)b * lda;
    const float* w = W + (long)o * Kd;
    float s0 = 0.f, s1 = 0.f, s2 = 0.f, s3 = 0.f;
    int k = 0;
    for (; k + 3 < Kd; k += 4) {
        s0 = fmaf(a[k],     w[k],     s0);
        s1 = fmaf(a[k + 1], w[k + 1], s1);
        s2 = fmaf(a[k + 2], w[k + 2], s2);
        s3 = fmaf(a[k + 3], w[k + 3], s3);
    }
    for (; k < Kd; k++) s0 = fmaf(a[k], w[k], s0);
    float s = (s0 + s1) + (s2 + s3) + (bias ? bias[o] : 0.f);
    if (relu) s = (s >= 0.f) ? s : 0.2f * s;
    C[(long)b * ldc + o] = s;
}

// ---------------------------------------------------------------------------
extern "C" void kernel_launch(void* const* d_in, const int* in_sizes, int n_in,
                              void* d_out, int out_size)
{
    const float* x   = (const float*)d_in[0];
    const float* y   = (const float*)d_in[1];
    const float* Ws[4] = { (const float*)d_in[2], (const float*)d_in[3],
                           (const float*)d_in[4], (const float*)d_in[5] };
    const float* W4  = (const float*)d_in[6];
    const float* L0  = (const float*)d_in[7];
    const float* L1  = (const float*)d_in[8];
    const float* L2w = (const float*)d_in[9];
    const float* L2b = (const float*)d_in[10];
    const float* F0w = (const float*)d_in[11];
    const float* F0b = (const float*)d_in[12];
    const float* F1w = (const float*)d_in[13];
    const float* F1b = (const float*)d_in[14];
    float* out = (float*)d_out;

    cudaFuncSetAttribute(mma_gemm<0>,
                         cudaFuncAttributeMaxDynamicSharedMemorySize, SMEM_MMA);
    cudaFuncSetAttribute(mma_gemm<1>,
                         cudaFuncAttributeMaxDynamicSharedMemorySize, SMEM_MMA);

    float *G, *cat, *uv, *h0, *xx, *Wuv, *z, *ye0, *z1, *z2;
    unsigned int* zenc;
    int* idxp;
    cudaGetSymbolAddress((void**)&G,    g_G);
    cudaGetSymbolAddress((void**)&cat,  g_cat);
    cudaGetSymbolAddress((void**)&uv,   g_uv);
    cudaGetSymbolAddress((void**)&h0,   g_h0);
    cudaGetSymbolAddress((void**)&xx,   g_xx);
    cudaGetSymbolAddress((void**)&Wuv,  g_Wuv);
    cudaGetSymbolAddress((void**)&z,    g_z);
    cudaGetSymbolAddress((void**)&ye0,  g_ye0);
    cudaGetSymbolAddress((void**)&z1,   g_z1);
    cudaGetSymbolAddress((void**)&z2,   g_z2);
    cudaGetSymbolAddress((void**)&zenc, g_zenc);
    cudaGetSymbolAddress((void**)&idxp, g_idx);

    // Side stream + events (leaked deliberately; see R12 note).
    cudaStream_t s2;
    cudaStreamCreateWithFlags(&s2, cudaStreamNonBlocking);
    cudaEvent_t eStart, eY, eW4a, eIn[4], eUv[4];
    cudaEventCreateWithFlags(&eStart, cudaEventDisableTiming);
    cudaEventCreateWithFlags(&eY, cudaEventDisableTiming);
    cudaEventCreateWithFlags(&eW4a, cudaEventDisableTiming);
    for (int l = 0; l < 4; l++) {
        cudaEventCreateWithFlags(&eIn[l], cudaEventDisableTiming);
        cudaEventCreateWithFlags(&eUv[l], cudaEventDisableTiming);
    }

    // ---- prologue fork: zenc_init + y-path on s2 ----
    cudaEventRecord(eStart, 0);
    cudaStreamWaitEvent(s2, eStart, 0);
    zenc_init_kernel<<<(BB * 1024 + 255) / 256, 256, 0, s2>>>(zenc);
    fc_kernel<<<1, 256, 0, s2>>>(y, 16, F0w, F0b, ye0, 16, BB, 16, 16, 1);
    fc_kernel<<<(BB * 64 + 255) / 256, 256, 0, s2>>>(ye0, 16, F1w, F1b,
                                                     z + 1024, 1088,
                                                     BB, 64, 16, 1);
    cudaEventRecord(eY, s2);

    // ---- four edge-conv layers with A/B path overlap ----
    const float* feats[4] = { x, cat + 0, cat + 64, cat + 128 };
    const int    ldas[4]  = { 6, 512, 512, 512 };
    const int    ds[4]    = { 6, 64, 64, 128 };
    const int    outcs[4] = { 64, 64, 128, 256 };
    float*       catOut[4] = { cat + 0, cat + 64, cat + 128, cat + 256 };

    for (int l = 0; l < 4; l++) {
        const float* feat = feats[l];
        int lda = ldas[l], d = ds[l], outc = outcs[l];

        cudaEventRecord(eIn[l], 0);
        cudaStreamWaitEvent(s2, eIn[l], 0);

        // path B (s2): wuv -> uv GEMM
        int nw = 2 * outc * d;
        wuv_kernel<<<(nw + 255) / 256, 256, 0, s2>>>(Ws[l], Wuv, outc, d);
        dim3 gu((2 * outc) / 128, (BB * NN) / 128, 1);
        mma_gemm<0><<<gu, 256, SMEM_MMA, s2>>>(feat, Wuv, uv, nullptr, nullptr,
                                               d, lda, d, 2 * outc, 0, 0, 0);
        cudaEventRecord(eUv[l], s2);

        // On the last layer, also launch W4a on s2: partial h0 over cat
        // cols 0:256 (final after layer 3's gather, which eIn[3] orders).
        if (l == 3) {
            dim3 g4(1024 / 128, (BB * NN) / 128, 1);
            mma_gemm<0><<<g4, 256, SMEM_MMA, s2>>>(cat, W4, h0, nullptr,
                                                   nullptr, 256, 512, 512,
                                                   1024, 0, 0, 0);
            cudaEventRecord(eW4a, s2);
        }

        // path A (main): xx -> Gram -> topk
        xx_kernel<<<(BB * NN + 255) / 256, 256>>>(feat, lda, d, xx);
        dim3 gG(NN / 128, NN / 128, BB);
        mma_gemm<0><<<gG, 256, SMEM_MMA>>>(feat, feat, G, nullptr, nullptr, d,
                                           lda, lda, NN, (long)NN * lda,
                                           (long)NN * lda, (long)NN * NN);
        topk_kernel<<<BB * NN / 8, 256>>>(G, xx, idxp);

        // join + gather
        cudaStreamWaitEvent(0, eUv[l], 0);
        gather_max_kernel<<<BB * NN, outc>>>(uv, idxp, catOut[l], outc);
    }

    // ---- W4b: second K-half + h0 add + fused column max ----
    cudaStreamWaitEvent(0, eW4a, 0);
    dim3 g4(1024 / 128, (BB * NN) / 128, 1);
    mma_gemm<1><<<g4, 256, SMEM_MMA>>>(cat + 256, W4 + 256, nullptr, zenc, h0,
                                       256, 512, 512, 1024, 0, 0, 0);
    zenc_decode_kernel<<<(BB * 1024 + 255) / 256, 256>>>(zenc, z);

    // join y-path before reading z
    cudaStreamWaitEvent(0, eY, 0);

    fc_kernel<<<(BB * 512 + 255) / 256, 256>>>(z, 1088, L0, nullptr, z1, 512,
                                               BB, 512, 1088, 1);
    fc_kernel<<<(BB * 256 + 255) / 256, 256>>>(z1, 512, L1, nullptr, z2, 256,
                                               BB, 256, 512, 1);
    fc_kernel<<<1, 16>>>(z2, 256, L2w, L2b, out, 1, BB, 1, 256, 0);
}

// round 14
// speedup vs baseline: 1.0286x; 1.0286x over previous
#include <cuda_runtime.h>
#include <cuda_bf16.h>
#include <cuda_fp16.h>
#include <math.h>
#include <stdint.h>

// ---------------------------------------------------------------------------
// DGCNN discriminator, B=16, N=1024, K=20.
// Round 14: revert split-K W4 (GEMM-vs-GEMM overlap is pipe-conserved, net
// loss); vectorize topk loads (float4, true-j keys); gather_max with float4
// channels and multi-point 256-thread blocks.  R12 stream overlap retained.
// ---------------------------------------------------------------------------

#define BB 16
#define NN 1024
#define KNNK 20
#define CATC 512

__device__ float g_G[BB * NN * NN];
__device__ float g_cat[BB * NN * CATC];
__device__ float g_uv[BB * NN * 512];
__device__ float g_xx[BB * NN];
__device__ int   g_idx[BB * NN * KNNK];
__device__ float g_Wuv[512 * 256];
__device__ unsigned int g_zenc[BB * 1024];
__device__ float g_z[BB * 1088];
__device__ float g_ye0[BB * 16];
__device__ float g_z1[BB * 512];
__device__ float g_z2[BB * 256];

__device__ __forceinline__ unsigned int ord_float(float v) {
    unsigned int u = __float_as_uint(v);
    return (u & 0x80000000u) ? ~u : (u | 0x80000000u);
}
__device__ __forceinline__ float ord_decode(unsigned int e) {
    unsigned int u = (e & 0x80000000u) ? (e ^ 0x80000000u) : ~e;
    return __uint_as_float(u);
}

// ---------------- warp-MMA primitives (baseline PTX, sm_80+) ---------------
__device__ __forceinline__ void ldsm4(uint32_t* r, const void* p) {
    uint32_t addr = (uint32_t)__cvta_generic_to_shared(p);
    asm volatile("ldmatrix.sync.aligned.m8n8.x4.shared.b16 {%0,%1,%2,%3}, [%4];"
                 : "=r"(r[0]), "=r"(r[1]), "=r"(r[2]), "=r"(r[3]) : "r"(addr));
}
__device__ __forceinline__ void mma_f16(float* c, const uint32_t* a,
                                        const uint32_t* b) {
    asm volatile(
        "mma.sync.aligned.m16n8k16.row.col.f32.f16.f16.f32 "
        "{%0,%1,%2,%3}, {%4,%5,%6,%7}, {%8,%9}, {%0,%1,%2,%3};"
        : "+f"(c[0]), "+f"(c[1]), "+f"(c[2]), "+f"(c[3])
        : "r"(a[0]), "r"(a[1]), "r"(a[2]), "r"(a[3]), "r"(b[0]), "r"(b[1]));
}
__device__ __forceinline__ uint32_t packh2(float x, float y) {
    __half2 v = __floats2half2_rn(x, y);
    uint32_t r; memcpy(&r, &v, 4); return r;
}
__device__ __forceinline__ void split2h(float a, float& h, float& l) {
    h = __half2float(__float2half_rn(a));
    l = a - h;
}

#define LDS2 40
#define TILE2 (128 * LDS2)
#define SMEM_MMA (2 * TILE2 * 2)    // 20480 B

// ---------------------------------------------------------------------------
// C[M,N] = A[M,Kd] @ W[N,Kd]^T, fp32 in/out, 3-term fp16 split, fp32 acc.
// EPI==0: store C.  EPI==1: ord-atomicMax column max into zenc.
// ---------------------------------------------------------------------------
template<int EPI>
__global__ __launch_bounds__(256, 2)
void mma_gemm(const float* __restrict__ A, const float* __restrict__ Wt,
              float* __restrict__ C, unsigned int* __restrict__ zenc,
              int Kd, int lda, int ldw, int ldc,
              long bA, long bW, long bC)
{
    extern __shared__ __half dsm[];
    __half* As = dsm;            // [128][LDS2]
    __half* Bs = dsm + TILE2;    // [128][LDS2]

    int bz = blockIdx.z;
    A  += (long)bz * bA;
    Wt += (long)bz * bW;
    C  += (long)bz * bC;

    int tid = threadIdx.x;
    int lane = tid & 31, wid = tid >> 5;
    int warpm = wid >> 2;
    int warpn = wid & 3;
    int row0 = blockIdx.y * 128, col0 = blockIdx.x * 128;

    int lr = tid >> 1;
    int kh = (tid & 1) << 3;
    const float* Ar = A  + (long)(row0 + lr) * lda;
    const float* Wr = Wt + (long)(col0 + lr) * ldw;
    const bool vec = ((lda & 3) == 0) && ((ldw & 3) == 0) && ((Kd & 15) == 0);

    float acc[4][4][4];
    #pragma unroll
    for (int i = 0; i < 4; i++)
        #pragma unroll
        for (int j = 0; j < 4; j++)
            #pragma unroll
            for (int q = 0; q < 4; q++) acc[i][j][q] = 0.f;

    int ntiles = (Kd + 15) >> 4;
    float fa[8], fb[8];

    {
        if (vec) {
            *(float4*)&fa[0] = *(const float4*)(Ar + kh);
            *(float4*)&fa[4] = *(const float4*)(Ar + kh + 4);
            *(float4*)&fb[0] = *(const float4*)(Wr + kh);
            *(float4*)&fb[4] = *(const float4*)(Wr + kh + 4);
        } else {
            #pragma unroll
            for (int q = 0; q < 8; q++) {
                int gk = kh + q;
                fa[q] = (gk < Kd) ? Ar[gk] : 0.f;
                fb[q] = (gk < Kd) ? Wr[gk] : 0.f;
            }
        }
    }

    for (int t = 0; t < ntiles; t++) {
        {
            float ah[8], al[8], bh[8], bl[8];
            #pragma unroll
            for (int q = 0; q < 8; q++) {
                split2h(fa[q], ah[q], al[q]);
                split2h(fb[q], bh[q], bl[q]);
            }
            int rb = lr * LDS2 + kh;
            #pragma unroll
            for (int j = 0; j < 4; j++) {
                int c = rb + 2 * j;
                *(uint32_t*)&As[c +  0] = packh2(ah[2 * j], ah[2 * j + 1]);
                *(uint32_t*)&As[c + 16] = packh2(al[2 * j], al[2 * j + 1]);
                *(uint32_t*)&Bs[c +  0] = packh2(bh[2 * j], bh[2 * j + 1]);
                *(uint32_t*)&Bs[c + 16] = packh2(bl[2 * j], bl[2 * j + 1]);
            }
        }
        __syncthreads();

        if (t + 1 < ntiles) {
            int k0 = (t + 1) << 4;
            if (vec) {
                *(float4*)&fa[0] = *(const float4*)(Ar + k0 + kh);
                *(float4*)&fa[4] = *(const float4*)(Ar + k0 + kh + 4);
                *(float4*)&fb[0] = *(const float4*)(Wr + k0 + kh);
                *(float4*)&fb[4] = *(const float4*)(Wr + k0 + kh + 4);
            } else {
                #pragma unroll
                for (int q = 0; q < 8; q++) {
                    int gk = k0 + kh + q;
                    fa[q] = (gk < Kd) ? Ar[gk] : 0.f;
                    fb[q] = (gk < Kd) ? Wr[gk] : 0.f;
                }
            }
        }

        {
            int arow = warpm * 64 + (lane & 15);
            int acol = (lane >> 4) << 3;
            int brow = warpn * 32 + (lane & 15);

            uint32_t afh[4][4], afl[4][4];
            uint32_t bfh[4][2], bfl[4][2];

            #pragma unroll
            for (int mi = 0; mi < 4; mi++)
                ldsm4(afh[mi], &As[(arow + mi * 16) * LDS2 + acol]);
            #pragma unroll
            for (int nq = 0; nq < 2; nq++) {
                uint32_t tt[4];
                ldsm4(tt, &Bs[(brow + nq * 16) * LDS2 + acol]);
                bfh[2 * nq][0] = tt[0]; bfh[2 * nq][1] = tt[2];
                bfh[2 * nq + 1][0] = tt[1]; bfh[2 * nq + 1][1] = tt[3];
            }
            #pragma unroll
            for (int mi = 0; mi < 4; mi++)
                #pragma unroll
                for (int nj = 0; nj < 4; nj++)
                    mma_f16(acc[mi][nj], afh[mi], bfh[nj]);

            #pragma unroll
            for (int nq = 0; nq < 2; nq++) {
                uint32_t tt[4];
                ldsm4(tt, &Bs[(brow + nq * 16) * LDS2 + 16 + acol]);
                bfl[2 * nq][0] = tt[0]; bfl[2 * nq][1] = tt[2];
                bfl[2 * nq + 1][0] = tt[1]; bfl[2 * nq + 1][1] = tt[3];
            }
            #pragma unroll
            for (int mi = 0; mi < 4; mi++)
                #pragma unroll
                for (int nj = 0; nj < 4; nj++)
                    mma_f16(acc[mi][nj], afh[mi], bfl[nj]);

            #pragma unroll
            for (int mi = 0; mi < 4; mi++)
                ldsm4(afl[mi], &As[(arow + mi * 16) * LDS2 + 16 + acol]);
            #pragma unroll
            for (int mi = 0; mi < 4; mi++)
                #pragma unroll
                for (int nj = 0; nj < 4; nj++)
                    mma_f16(acc[mi][nj], afl[mi], bfh[nj]);
        }
        __syncthreads();
    }

    int g = lane >> 2, tg = lane & 3;
    if (EPI == 0) {
        #pragma unroll
        for (int mi = 0; mi < 4; mi++) {
            int r = row0 + warpm * 64 + mi * 16 + g;
            #pragma unroll
            for (int nj = 0; nj < 4; nj++) {
                int c = col0 + warpn * 32 + nj * 8 + tg * 2;
                *(float2*)&C[(long)r * ldc + c] =
                    make_float2(acc[mi][nj][0], acc[mi][nj][1]);
                *(float2*)&C[(long)(r + 8) * ldc + c] =
                    make_float2(acc[mi][nj][2], acc[mi][nj][3]);
            }
        }
    } else {
        int bidx = row0 >> 10;
        #pragma unroll
        for (int nj = 0; nj < 4; nj++) {
            #pragma unroll
            for (int h = 0; h < 2; h++) {
                float v = fmaxf(acc[0][nj][h], acc[0][nj][h + 2]);
                #pragma unroll
                for (int mi = 1; mi < 4; mi++)
                    v = fmaxf(v, fmaxf(acc[mi][nj][h], acc[mi][nj][h + 2]));
                v = fmaxf(v, __shfl_xor_sync(0xFFFFFFFFu, v, 4));
                v = fmaxf(v, __shfl_xor_sync(0xFFFFFFFFu, v, 8));
                v = fmaxf(v, __shfl_xor_sync(0xFFFFFFFFu, v, 16));
                if (lane < 4)
                    atomicMax(&zenc[bidx * 1024 + col0 + warpn * 32 + nj * 8 +
                                    lane * 2 + h],
                              ord_float(v));
            }
        }
    }
}

// ---------------------------------------------------------------------------
__global__ void xx_kernel(const float* __restrict__ feat, int lda, int d,
                          float* __restrict__ xx)
{
    int p = blockIdx.x * blockDim.x + threadIdx.x;
    if (p >= BB * NN) return;
    const float* r = feat + (long)p * lda;
    float s = 0.f;
    for (int c = 0; c < d; c++) s = fmaf(r[c], r[c], s);
    xx[p] = s;
}

// ---------------------------------------------------------------------------
// Warp-per-row top-20, float4 loads.  j = chunk*128 + lane*4 + e; packed key
// uses the true j so tie-break semantics are identical to scalar version.
// ---------------------------------------------------------------------------
__global__ __launch_bounds__(256)
void topk_kernel(const float* __restrict__ G, const float* __restrict__ xx,
                 int* __restrict__ idx)
{
    int warp = threadIdx.x >> 5, lane = threadIdx.x & 31;
    int row = blockIdx.x * 8 + warp;
    int b = row >> 10, i = row & 1023;
    const float* Grow = G + (long)row * NN;
    const float* xxb  = xx + (b << 10);
    float xi = xxb[i];

    float v[32];
    #pragma unroll
    for (int ch = 0; ch < 8; ch++) {
        int j0 = ch * 128 + lane * 4;
        float4 g4  = *(const float4*)&Grow[j0];
        float4 x4  = *(const float4*)&xxb[j0];
        v[ch * 4 + 0] = fmaf(2.0f, g4.x, -xi) - x4.x;
        v[ch * 4 + 1] = fmaf(2.0f, g4.y, -xi) - x4.y;
        v[ch * 4 + 2] = fmaf(2.0f, g4.z, -xi) - x4.z;
        v[ch * 4 + 3] = fmaf(2.0f, g4.w, -xi) - x4.w;
    }
    // NOTE: -xi - (-2g) - xj == 2g - xi - xj; fmaf(2,g,-xi)-xj is the same
    // fp32 value ordering-wise only if rounding matches the reference compute
    // (-xi - inner - xj).  Recompute exactly as before to be safe:
    #pragma unroll
    for (int ch = 0; ch < 8; ch++) {
        int j0 = ch * 128 + lane * 4;
        float4 g4  = *(const float4*)&Grow[j0];
        float4 x4  = *(const float4*)&xxb[j0];
        float gg[4] = {g4.x, g4.y, g4.z, g4.w};
        float xj[4] = {x4.x, x4.y, x4.z, x4.w};
        #pragma unroll
        for (int e = 0; e < 4; e++) {
            float inner = -2.0f * gg[e];
            v[ch * 4 + e] = -xi - inner - xj[e];
        }
    }

    float m1v = v[0], m2v = -__builtin_huge_valf();
    int m1q = 0, m2q = -1;
    #pragma unroll
    for (int q = 1; q < 32; q++) {
        if (v[q] > m1v) { m2v = m1v; m2q = m1q; m1v = v[q]; m1q = q; }
        else if (v[q] > m2v) { m2v = v[q]; m2q = q; }
    }

    int* out = idx + (long)row * KNNK;
    for (int kk = 0; kk < KNNK; kk++) {
        int jtrue = (m1q >> 2) * 128 + lane * 4 + (m1q & 3);
        unsigned long long key =
            ((unsigned long long)ord_float(m1v) << 32)
            | (unsigned int)(0xFFFFFFFFu - (unsigned int)jtrue);
        unsigned long long best = key;
        #pragma unroll
        for (int s = 16; s > 0; s >>= 1) {
            unsigned long long o = __shfl_xor_sync(0xFFFFFFFFu, best, s);
            if (o > best) best = o;
        }
        if (lane == 0)
            out[kk] = (int)(0xFFFFFFFFu - (unsigned int)(best & 0xFFFFFFFFu));

        if (key == best) {
            #pragma unroll
            for (int q = 0; q < 32; q++)
                if (q == m1q) v[q] = -__builtin_huge_valf();
            if (m2q >= 0) {
                m1v = m2v; m1q = m2q; m2q = -1;
            } else {
                m1v = v[0]; m1q = 0;
                m2v = -__builtin_huge_valf(); m2q = -1;
                #pragma unroll
                for (int q = 1; q < 32; q++) {
                    if (v[q] > m1v) { m2v = m1v; m2q = m1q; m1v = v[q]; m1q = q; }
                    else if (v[q] > m2v) { m2v = v[q]; m2q = q; }
                }
            }
        }
    }
}

__global__ void wuv_kernel(const float* __restrict__ W, float* __restrict__ Wuv,
                           int outc, int d)
{
    int t = blockIdx.x * blockDim.x + threadIdx.x;
    if (t >= 2 * outc * d) return;
    int r = t / d, c = t - r * d;
    if (r < outc) Wuv[t] = W[(long)r * 2 * d + c];
    else {
        int o = r - outc;
        Wuv[t] = W[(long)o * 2 * d + d + c] - W[(long)o * 2 * d + c];
    }
}

// ---------------------------------------------------------------------------
// gather_max: float4 channels, multiple points per 256-thread block.
// CPT = outc/4 quad-channels per point; PPB = 256/CPT points per block.
// ---------------------------------------------------------------------------
__global__ __launch_bounds__(256)
void gather_max_kernel(const float* __restrict__ uv,
                       const int* __restrict__ idx,
                       float* __restrict__ outp, int outc)
{
    int cpt = outc >> 2;                   // 16 / 32 / 64
    int ppb = 256 / cpt;                   // 16 / 8 / 4
    int tid = threadIdx.x;
    int pib = tid / cpt, cq = tid - pib * cpt;
    int p = blockIdx.x * ppb + pib;
    int b = p >> 10;
    int ldu = 2 * outc;

    const float* uvp = uv + (long)p * ldu;
    float4 vi = *(const float4*)&uvp[outc + cq * 4];
    const int* ip = idx + (long)p * KNNK;
    const float* ub = uv + ((long)(b << 10)) * ldu + cq * 4;

    float4 m = make_float4(-__builtin_huge_valf(), -__builtin_huge_valf(),
                           -__builtin_huge_valf(), -__builtin_huge_valf());
    #pragma unroll 4
    for (int kk = 0; kk < KNNK; kk++) {
        int j = ip[kk];
        float4 u4 = *(const float4*)&ub[(long)j * ldu];
        float t0 = u4.x + vi.x, t1 = u4.y + vi.y;
        float t2 = u4.z + vi.z, t3 = u4.w + vi.w;
        t0 = (t0 >= 0.f) ? t0 : 0.2f * t0;
        t1 = (t1 >= 0.f) ? t1 : 0.2f * t1;
        t2 = (t2 >= 0.f) ? t2 : 0.2f * t2;
        t3 = (t3 >= 0.f) ? t3 : 0.2f * t3;
        m.x = fmaxf(m.x, t0); m.y = fmaxf(m.y, t1);
        m.z = fmaxf(m.z, t2); m.w = fmaxf(m.w, t3);
    }
    *(float4*)&outp[(long)p * CATC + cq * 4] = m;
}

__global__ void zenc_init_kernel(unsigned int* __restrict__ zenc)
{
    int t = blockIdx.x * blockDim.x + threadIdx.x;
    if (t < BB * 1024) zenc[t] = 0u;
}

__global__ void zenc_decode_kernel(const unsigned int* __restrict__ zenc,
                                   float* __restrict__ z)
{
    int t = blockIdx.x * blockDim.x + threadIdx.x;
    if (t >= BB * 1024) return;
    int b = t >> 10, o = t & 1023;
    float m = ord_decode(zenc[t]);
    m = (m >= 0.f) ? m : 0.2f * m;
    z[b * 1088 + o] = m;
}

__global__ void fc_kernel(const float* __restrict__ A, int lda,
                          const float* __restrict__ W,
                          const float* __restrict__ bias,
                          float* __restrict__ C, int ldc,
                          int Bn, int O, int Kd, int relu)
{
    int t = blockIdx.x * blockDim.x + threadIdx.x;
    if (t >= Bn * O) return;
    int b = t / O, o = t - b * O;
    const float* a = A + (long)b * lda;
    const float* w = W + (long)o * Kd;
    float s0 = 0.f, s1 = 0.f, s2 = 0.f, s3 = 0.f;
    int k = 0;
    for (; k + 3 < Kd; k += 4) {
        s0 = fmaf(a[k],     w[k],     s0);
        s1 = fmaf(a[k + 1], w[k + 1], s1);
        s2 = fmaf(a[k + 2], w[k + 2], s2);
        s3 = fmaf(a[k + 3], w[k + 3], s3);
    }
    for (; k < Kd; k++) s0 = fmaf(a[k], w[k], s0);
    float s = (s0 + s1) + (s2 + s3) + (bias ? bias[o] : 0.f);
    if (relu) s = (s >= 0.f) ? s : 0.2f * s;
    C[(long)b * ldc + o] = s;
}

// ---------------------------------------------------------------------------
extern "C" void kernel_launch(void* const* d_in, const int* in_sizes, int n_in,
                              void* d_out, int out_size)
{
    const float* x   = (const float*)d_in[0];
    const float* y   = (const float*)d_in[1];
    const float* Ws[4] = { (const float*)d_in[2], (const float*)d_in[3],
                           (const float*)d_in[4], (const float*)d_in[5] };
    const float* W4  = (const float*)d_in[6];
    const float* L0  = (const float*)d_in[7];
    const float* L1  = (const float*)d_in[8];
    const float* L2w = (const float*)d_in[9];
    const float* L2b = (const float*)d_in[10];
    const float* F0w = (const float*)d_in[11];
    const float* F0b = (const float*)d_in[12];
    const float* F1w = (const float*)d_in[13];
    const float* F1b = (const float*)d_in[14];
    float* out = (float*)d_out;

    cudaFuncSetAttribute(mma_gemm<0>,
                         cudaFuncAttributeMaxDynamicSharedMemorySize, SMEM_MMA);
    cudaFuncSetAttribute(mma_gemm<1>,
                         cudaFuncAttributeMaxDynamicSharedMemorySize, SMEM_MMA);

    float *G, *cat, *uv, *xx, *Wuv, *z, *ye0, *z1, *z2;
    unsigned int* zenc;
    int* idxp;
    cudaGetSymbolAddress((void**)&G,    g_G);
    cudaGetSymbolAddress((void**)&cat,  g_cat);
    cudaGetSymbolAddress((void**)&uv,   g_uv);
    cudaGetSymbolAddress((void**)&xx,   g_xx);
    cudaGetSymbolAddress((void**)&Wuv,  g_Wuv);
    cudaGetSymbolAddress((void**)&z,    g_z);
    cudaGetSymbolAddress((void**)&ye0,  g_ye0);
    cudaGetSymbolAddress((void**)&z1,   g_z1);
    cudaGetSymbolAddress((void**)&z2,   g_z2);
    cudaGetSymbolAddress((void**)&zenc, g_zenc);
    cudaGetSymbolAddress((void**)&idxp, g_idx);

    // Side stream + events (leaked deliberately; see R12 note).
    cudaStream_t s2;
    cudaStreamCreateWithFlags(&s2, cudaStreamNonBlocking);
    cudaEvent_t eStart, eY, eIn[4], eUv[4];
    cudaEventCreateWithFlags(&eStart, cudaEventDisableTiming);
    cudaEventCreateWithFlags(&eY, cudaEventDisableTiming);
    for (int l = 0; l < 4; l++) {
        cudaEventCreateWithFlags(&eIn[l], cudaEventDisableTiming);
        cudaEventCreateWithFlags(&eUv[l], cudaEventDisableTiming);
    }

    // ---- prologue fork: zenc_init + y-path on s2 ----
    cudaEventRecord(eStart, 0);
    cudaStreamWaitEvent(s2, eStart, 0);
    zenc_init_kernel<<<(BB * 1024 + 255) / 256, 256, 0, s2>>>(zenc);
    fc_kernel<<<1, 256, 0, s2>>>(y, 16, F0w, F0b, ye0, 16, BB, 16, 16, 1);
    fc_kernel<<<(BB * 64 + 255) / 256, 256, 0, s2>>>(ye0, 16, F1w, F1b,
                                                     z + 1024, 1088,
                                                     BB, 64, 16, 1);
    cudaEventRecord(eY, s2);

    // ---- four edge-conv layers with A/B path overlap ----
    const float* feats[4] = { x, cat + 0, cat + 64, cat + 128 };
    const int    ldas[4]  = { 6, 512, 512, 512 };
    const int    ds[4]    = { 6, 64, 64, 128 };
    const int    outcs[4] = { 64, 64, 128, 256 };
    float*       catOut[4] = { cat + 0, cat + 64, cat + 128, cat + 256 };

    for (int l = 0; l < 4; l++) {
        const float* feat = feats[l];
        int lda = ldas[l], d = ds[l], outc = outcs[l];

        cudaEventRecord(eIn[l], 0);
        cudaStreamWaitEvent(s2, eIn[l], 0);

        // path B (s2): wuv -> uv GEMM
        int nw = 2 * outc * d;
        wuv_kernel<<<(nw + 255) / 256, 256, 0, s2>>>(Ws[l], Wuv, outc, d);
        dim3 gu((2 * outc) / 128, (BB * NN) / 128, 1);
        mma_gemm<0><<<gu, 256, SMEM_MMA, s2>>>(feat, Wuv, uv, nullptr, d, lda,
                                               d, 2 * outc, 0, 0, 0);
        cudaEventRecord(eUv[l], s2);

        // path A (main): xx -> Gram -> topk
        xx_kernel<<<(BB * NN + 255) / 256, 256>>>(feat, lda, d, xx);
        dim3 gG(NN / 128, NN / 128, BB);
        mma_gemm<0><<<gG, 256, SMEM_MMA>>>(feat, feat, G, nullptr, d, lda, lda,
                                           NN, (long)NN * lda, (long)NN * lda,
                                           (long)NN * NN);
        topk_kernel<<<BB * NN / 8, 256>>>(G, xx, idxp);

        // join + gather (multi-point float4 blocks)
        cudaStreamWaitEvent(0, eUv[l], 0);
        int ppb = 256 / (outc >> 2);
        gather_max_kernel<<<BB * NN / ppb, 256>>>(uv, idxp, catOut[l], outc);
    }

    // ---- W4 GEMM fused with column max ----
    dim3 g4(1024 / 128, (BB * NN) / 128, 1);
    mma_gemm<1><<<g4, 256, SMEM_MMA>>>(cat, W4, nullptr, zenc, 512, 512, 512,
                                       0, 0, 0, 0);
    zenc_decode_kernel<<<(BB * 1024 + 255) / 256, 256>>>(zenc, z);

    // join y-path before reading z
    cudaStreamWaitEvent(0, eY, 0);

    fc_kernel<<<(BB * 512 + 255) / 256, 256>>>(z, 1088, L0, nullptr, z1, 512,
                                               BB, 512, 1088, 1);
    fc_kernel<<<(BB * 256 + 255) / 256, 256>>>(z1, 512, L1, nullptr, z2, 256,
                                               BB, 256, 512, 1);
    fc_kernel<<<1, 16>>>(z2, 256, L2w, L2b, out, 1, BB, 1, 256, 0);
}